// round 1
// baseline (speedup 1.0000x reference)
#include <cuda_runtime.h>
#include <math.h>

#define NIMG 64
#define C_IN 512
#define C_MID 128
#define HH 28
#define WW 28
#define HW 784
#define BN_EPS 1e-5f

// Scratch (no allocations allowed)
__device__ float g_t1[(size_t)NIMG * C_MID * HW];
__device__ float g_t2[(size_t)NIMG * C_MID * HW];
__device__ float g_s1[C_MID], g_h1[C_MID];
__device__ float g_s2[C_MID], g_h2[C_MID];
__device__ float g_s3[C_IN], g_h3[C_IN];

// ---------------------------------------------------------------------------
// Fold BN params into per-channel scale/shift
// ---------------------------------------------------------------------------
__global__ void bnprep_kernel(
    const float* __restrict__ g1, const float* __restrict__ b1,
    const float* __restrict__ mu1, const float* __restrict__ var1,
    const float* __restrict__ g2, const float* __restrict__ b2,
    const float* __restrict__ mu2, const float* __restrict__ var2,
    const float* __restrict__ g3, const float* __restrict__ b3,
    const float* __restrict__ mu3, const float* __restrict__ var3)
{
    int c = threadIdx.x;
    if (c < C_MID) {
        float inv = g1[c] * rsqrtf(var1[c] + BN_EPS);
        g_s1[c] = inv; g_h1[c] = b1[c] - mu1[c] * inv;
        inv = g2[c] * rsqrtf(var2[c] + BN_EPS);
        g_s2[c] = inv; g_h2[c] = b2[c] - mu2[c] * inv;
    }
    if (c < C_IN) {
        float inv = g3[c] * rsqrtf(var3[c] + BN_EPS);
        g_s3[c] = inv; g_h3[c] = b3[c] - mu3[c] * inv;
    }
}

// ---------------------------------------------------------------------------
// 1x1 conv as per-image GEMM: C[n][mt*128+m][col] = sum_k A[mt*128+m][k]*B[n][k][col]
// CTA tile 128(M) x 112(cols), K chunks of 32, 16x16 threads, 8x7 per-thread.
// Epilogue: BN scale/shift (+ optional residual) + ReLU.
// ---------------------------------------------------------------------------
template <bool RESIDUAL>
__global__ __launch_bounds__(256, 2)
void gemm1x1_kernel(const float* __restrict__ A, const float* __restrict__ B,
                    float* __restrict__ Cout,
                    const float* __restrict__ scale, const float* __restrict__ shift,
                    const float* __restrict__ resid, int K, int Mtot)
{
    __shared__ __align__(16) float a_s[32 * 128];  // [kk][co]
    __shared__ __align__(16) float b_s[32 * 112];  // [kk][col]

    const int n = blockIdx.y;
    const int mt = blockIdx.z;
    const int col0 = blockIdx.x * 112;

    const float* Ab = A + (size_t)mt * 128 * K;
    const float* Bn = B + (size_t)n * K * HW + col0;

    const int t = threadIdx.x;
    const int tx = t & 15, ty = t >> 4;

    // A staging map: thread -> (co = t/2, 16 consecutive k at (t&1)*16)
    const int aco = t >> 1;
    const int akk = (t & 1) << 4;
    const float* ag = Ab + (size_t)aco * K + akk;
    // B staging map: thread -> (kk = t/8, cols (t&7) + 8j, j<14)
    const int brow = t >> 3;
    const int bcol = t & 7;
    const float* bg = Bn + brow * HW + bcol;

    float4 pa[4];
    float pb[14];
#pragma unroll
    for (int q = 0; q < 4; q++) pa[q] = *(const float4*)(ag + 4 * q);
#pragma unroll
    for (int j = 0; j < 14; j++) pb[j] = bg[8 * j];

    float acc[8][7];
#pragma unroll
    for (int i = 0; i < 8; i++)
#pragma unroll
        for (int j = 0; j < 7; j++) acc[i][j] = 0.f;

    for (int k0 = 0; k0 < K; k0 += 32) {
        __syncthreads();
#pragma unroll
        for (int q = 0; q < 4; q++) {
            a_s[(akk + 4 * q + 0) * 128 + aco] = pa[q].x;
            a_s[(akk + 4 * q + 1) * 128 + aco] = pa[q].y;
            a_s[(akk + 4 * q + 2) * 128 + aco] = pa[q].z;
            a_s[(akk + 4 * q + 3) * 128 + aco] = pa[q].w;
        }
#pragma unroll
        for (int j = 0; j < 14; j++) b_s[brow * 112 + bcol + 8 * j] = pb[j];
        __syncthreads();

        if (k0 + 32 < K) {
            const float* ag2 = ag + k0 + 32;
#pragma unroll
            for (int q = 0; q < 4; q++) pa[q] = *(const float4*)(ag2 + 4 * q);
            const float* bg2 = bg + (size_t)(k0 + 32) * HW;
#pragma unroll
            for (int j = 0; j < 14; j++) pb[j] = bg2[8 * j];
        }

#pragma unroll 8
        for (int kk = 0; kk < 32; kk++) {
            float4 a0 = *(const float4*)&a_s[kk * 128 + ty * 8];
            float4 a1 = *(const float4*)&a_s[kk * 128 + ty * 8 + 4];
            float av[8] = {a0.x, a0.y, a0.z, a0.w, a1.x, a1.y, a1.z, a1.w};
            float bv[7];
#pragma unroll
            for (int j = 0; j < 7; j++) bv[j] = b_s[kk * 112 + tx + 16 * j];
#pragma unroll
            for (int i = 0; i < 8; i++)
#pragma unroll
                for (int j = 0; j < 7; j++)
                    acc[i][j] = fmaf(av[i], bv[j], acc[i][j]);
        }
    }

#pragma unroll
    for (int i = 0; i < 8; i++) {
        int ch = mt * 128 + ty * 8 + i;
        float s = scale[ch], h = shift[ch];
        size_t ob = ((size_t)n * Mtot + ch) * HW + col0;
#pragma unroll
        for (int j = 0; j < 7; j++) {
            float v = fmaf(acc[i][j], s, h);
            if (RESIDUAL) v += resid[ob + tx + 16 * j];
            Cout[ob + tx + 16 * j] = fmaxf(v, 0.f);
        }
    }
}

// ---------------------------------------------------------------------------
// 3x3 conv, pad 1, 128->128. CTA = (image n, 4-row group g).
// Computes all 128 output channels x 112 spatial outputs.
// ---------------------------------------------------------------------------
__global__ __launch_bounds__(256, 2)
void conv3x3_kernel(const float* __restrict__ in, const float* __restrict__ w,
                    float* __restrict__ out,
                    const float* __restrict__ scale, const float* __restrict__ shift)
{
    __shared__ __align__(16) float w_s[8 * 9 * 128];  // [ci][tap][co]
    __shared__ __align__(16) float in_s[8 * 6 * 30];  // [ci][row(6)][col(30, padded)]

    const int n = blockIdx.y, g = blockIdx.x;
    const int t = threadIdx.x;
    const int tx = t & 15, ty = t >> 4;

    int off[7];
#pragma unroll
    for (int j = 0; j < 7; j++) {
        int p = tx + 16 * j;           // 0..111 within row group
        off[j] = (p / 28) * 30 + (p % 28);
    }
    const int r0 = g * 4 - 1;

    float acc[8][7];
#pragma unroll
    for (int i = 0; i < 8; i++)
#pragma unroll
        for (int j = 0; j < 7; j++) acc[i][j] = 0.f;

    const float* inb = in + (size_t)n * C_MID * HW;

    for (int ci0 = 0; ci0 < C_MID; ci0 += 8) {
        __syncthreads();
        // stage weights: 8 ci x 9 taps x 128 co = 9216 floats
        for (int i = t; i < 9216; i += 256) {
            int tap = i % 9;
            int r = i / 9;
            int ci = r & 7;
            int co = r >> 3;
            w_s[ci * 1152 + tap * 128 + co] = w[(size_t)co * 1152 + (ci0 + ci) * 9 + tap];
        }
        // stage input slab with halo: 8 ci x 6 rows x 30 cols (zero padded)
        for (int i = t; i < 1440; i += 256) {
            int col = i % 30;
            int rr = (i / 30) % 6;
            int ci = i / 180;
            int rin = r0 + rr, cin = col - 1;
            float v = 0.f;
            if ((unsigned)rin < 28u && (unsigned)cin < 28u)
                v = inb[(size_t)(ci0 + ci) * HW + rin * 28 + cin];
            in_s[i] = v;
        }
        __syncthreads();

#pragma unroll 1
        for (int ci = 0; ci < 8; ci++) {
#pragma unroll
            for (int kh = 0; kh < 3; kh++) {
#pragma unroll
                for (int kw = 0; kw < 3; kw++) {
                    const float* wp = &w_s[ci * 1152 + (kh * 3 + kw) * 128 + ty * 8];
                    float4 a0 = *(const float4*)wp;
                    float4 a1 = *(const float4*)(wp + 4);
                    float av[8] = {a0.x, a0.y, a0.z, a0.w, a1.x, a1.y, a1.z, a1.w};
                    int base = ci * 180 + kh * 30 + kw;
                    float bv[7];
#pragma unroll
                    for (int j = 0; j < 7; j++) bv[j] = in_s[base + off[j]];
#pragma unroll
                    for (int i = 0; i < 8; i++)
#pragma unroll
                        for (int j = 0; j < 7; j++)
                            acc[i][j] = fmaf(av[i], bv[j], acc[i][j]);
                }
            }
        }
    }

#pragma unroll
    for (int i = 0; i < 8; i++) {
        int ch = ty * 8 + i;
        float s = scale[ch], h = shift[ch];
        size_t ob = ((size_t)n * C_MID + ch) * HW + g * 112;
#pragma unroll
        for (int j = 0; j < 7; j++) {
            float v = fmaf(acc[i][j], s, h);
            out[ob + tx + 16 * j] = fmaxf(v, 0.f);
        }
    }
}

// ---------------------------------------------------------------------------
// Block floating point quant (in place): blocks of 32 channels share an
// exponent e=floor(log2(maxabs)) clipped to [-4,3]; round to 3 mantissa bits
// (round-half-even), clip to [-16,15] steps.
// ---------------------------------------------------------------------------
__global__ void quant_kernel(float* __restrict__ p, int C, int total)
{
    int idx = blockIdx.x * blockDim.x + threadIdx.x;
    if (idx >= total) return;
    int hw = idx % HW;
    int nb = idx / HW;
    int nblk = C >> 5;
    int b = nb % nblk;
    int n = nb / nblk;
    float* q = p + ((size_t)(n * C + b * 32)) * HW + hw;

    float v[32];
    float ma = 0.f;
#pragma unroll
    for (int c = 0; c < 32; c++) {
        v[c] = q[c * HW];
        ma = fmaxf(ma, fabsf(v[c]));
    }
    if (ma > 0.f) {
        int e;
        frexpf(ma, &e);            // ma = f*2^e, f in [0.5,1) => floor(log2 ma) = e-1
        int fe = e - 1;
        if (fe < -4) fe = -4;
        if (fe > 3) fe = 3;
        float step = ldexpf(1.0f, fe - 3);   // exact power of 2
        float inv = ldexpf(1.0f, 3 - fe);    // exact reciprocal
#pragma unroll
        for (int c = 0; c < 32; c++) {
            float r = rintf(v[c] * inv);     // round half to even, matches jnp.round
            r = fminf(fmaxf(r, -16.f), 15.f);
            q[c * HW] = r * step;
        }
    }
}

// ---------------------------------------------------------------------------
// Launcher
// ---------------------------------------------------------------------------
extern "C" void kernel_launch(void* const* d_in, const int* in_sizes, int n_in,
                              void* d_out, int out_size)
{
    (void)n_in; (void)out_size;

    // Detect input ordering: w2 (128*128*3*3 = 147456 elements) is unique.
    int iw1, iw2, iw3, ibn1, ibn2, ibn3;
    if (in_sizes[2] == 147456) {
        // dict order: x, w1, w2, w3, g1,b1,mu1,var1, g2,..., var3
        iw1 = 1; iw2 = 2; iw3 = 3; ibn1 = 4; ibn2 = 8; ibn3 = 12;
    } else {
        // signature order: x, w1, g1..var1, w2, g2..var2, w3, g3..var3
        iw1 = 1; ibn1 = 2; iw2 = 6; ibn2 = 7; iw3 = 11; ibn3 = 12;
    }

    const float* x  = (const float*)d_in[0];
    const float* w1 = (const float*)d_in[iw1];
    const float* w2 = (const float*)d_in[iw2];
    const float* w3 = (const float*)d_in[iw3];
    const float* g1 = (const float*)d_in[ibn1 + 0];
    const float* b1 = (const float*)d_in[ibn1 + 1];
    const float* mu1 = (const float*)d_in[ibn1 + 2];
    const float* var1 = (const float*)d_in[ibn1 + 3];
    const float* g2 = (const float*)d_in[ibn2 + 0];
    const float* b2 = (const float*)d_in[ibn2 + 1];
    const float* mu2 = (const float*)d_in[ibn2 + 2];
    const float* var2 = (const float*)d_in[ibn2 + 3];
    const float* g3 = (const float*)d_in[ibn3 + 0];
    const float* b3 = (const float*)d_in[ibn3 + 1];
    const float* mu3 = (const float*)d_in[ibn3 + 2];
    const float* var3 = (const float*)d_in[ibn3 + 3];
    float* out = (float*)d_out;

    float *t1, *t2, *s1, *h1, *s2, *h2, *s3, *h3;
    cudaGetSymbolAddress((void**)&t1, g_t1);
    cudaGetSymbolAddress((void**)&t2, g_t2);
    cudaGetSymbolAddress((void**)&s1, g_s1);
    cudaGetSymbolAddress((void**)&h1, g_h1);
    cudaGetSymbolAddress((void**)&s2, g_s2);
    cudaGetSymbolAddress((void**)&h2, g_h2);
    cudaGetSymbolAddress((void**)&s3, g_s3);
    cudaGetSymbolAddress((void**)&h3, g_h3);

    bnprep_kernel<<<1, 512>>>(g1, b1, mu1, var1, g2, b2, mu2, var2, g3, b3, mu3, var3);

    // conv1: [128x512] @ [512x784] per image, + BN1 + ReLU
    gemm1x1_kernel<false><<<dim3(7, NIMG, 1), 256>>>(w1, x, t1, s1, h1, nullptr, 512, C_MID);
    quant_kernel<<<(NIMG * 4 * HW + 255) / 256, 256>>>(t1, C_MID, NIMG * 4 * HW);

    // conv2: 3x3 + BN2 + ReLU
    conv3x3_kernel<<<dim3(7, NIMG), 256>>>(t1, w2, t2, s2, h2);
    quant_kernel<<<(NIMG * 4 * HW + 255) / 256, 256>>>(t2, C_MID, NIMG * 4 * HW);

    // conv3: [512x128] @ [128x784] per image, + BN3 + residual + ReLU
    gemm1x1_kernel<true><<<dim3(7, NIMG, 4), 256>>>(w3, t2, out, s3, h3, x, 128, C_IN);
    quant_kernel<<<(NIMG * 16 * HW + 255) / 256, 256>>>(out, C_IN, NIMG * 16 * HW);
}

// round 6
// speedup vs baseline: 2.0981x; 2.0981x over previous
#include <cuda_runtime.h>
#include <cuda_fp16.h>
#include <math.h>
#include <stdint.h>

#define NIMG 64
#define C_IN 512
#define C_MID 128
#define HW 784
#define BN_EPS 1e-5f
#define CH_PAD 960   // padded channel: 30 rows x 32 cols

// ---------------------------------------------------------------------------
// Scratch (__device__ globals; no allocations allowed)
// ---------------------------------------------------------------------------
__device__ float  g_t1f[(size_t)NIMG * C_MID * HW];   // conv1 out fp32 [n][c][hw]
// conv1 output, halo-padded fp16: pixel (y,x) of ch at ch*960 + (y+1)*32 + x+2.
// Borders never written -> stay zero.
__device__ __half g_t1p [(size_t)NIMG * C_MID * CH_PAD];
// shifted twin: value of t1p[i] lives at t1pm[i+1]
__device__ __half g_t1pm[(size_t)NIMG * C_MID * CH_PAD];
__device__ __half g_t2[(size_t)NIMG * C_MID * HW + 64];
__device__ __half g_w2h[9 * C_MID * C_MID], g_w2l[9 * C_MID * C_MID];  // 2^11-scaled
__device__ __half g_w3h[C_IN * C_MID], g_w3l[C_IN * C_MID];            // 2^11-scaled
__device__ float g_s1[C_MID], g_h1[C_MID];
__device__ float g_s2[C_MID], g_h2[C_MID];
__device__ float g_s3[C_IN], g_h3[C_IN];

#define INV2048 (1.0f / 2048.0f)

// ---------------------------------------------------------------------------
// Helpers
// ---------------------------------------------------------------------------
__device__ __forceinline__ uint32_t smem_u32(const void* p) {
    uint32_t a;
    asm("{ .reg .u64 t; cvta.to.shared.u64 t, %1; cvt.u32.u64 %0, t; }" : "=r"(a) : "l"(p));
    return a;
}
__device__ __forceinline__ uint32_t swz(uint32_t o) { return o ^ ((o >> 3) & 0x70); }

#define CPA16(d, s) asm volatile("cp.async.cg.shared.global [%0], [%1], 16;" :: "r"(d), "l"(s))
#define CPA4(d, s)  asm volatile("cp.async.ca.shared.global [%0], [%1], 4;"  :: "r"(d), "l"(s))
#define CPCOMMIT()  asm volatile("cp.async.commit_group;" ::: "memory")
#define CPWAIT1()   asm volatile("cp.async.wait_group 1;" ::: "memory")
#define CPWAIT0()   asm volatile("cp.async.wait_group 0;" ::: "memory")

__device__ __forceinline__ void ldsm_x4(uint32_t* a, uint32_t addr) {
    asm volatile("ldmatrix.sync.aligned.m8n8.x4.shared.b16 {%0,%1,%2,%3}, [%4];"
                 : "=r"(a[0]), "=r"(a[1]), "=r"(a[2]), "=r"(a[3]) : "r"(addr));
}
__device__ __forceinline__ void ldsm_x2t(uint32_t& b0, uint32_t& b1, uint32_t addr) {
    asm volatile("ldmatrix.sync.aligned.m8n8.x2.trans.shared.b16 {%0,%1}, [%2];"
                 : "=r"(b0), "=r"(b1) : "r"(addr));
}
__device__ __forceinline__ void mma16816(float* c, const uint32_t* a, uint32_t b0, uint32_t b1) {
    asm volatile("mma.sync.aligned.m16n8k16.row.col.f32.f16.f16.f32 "
                 "{%0,%1,%2,%3},{%4,%5,%6,%7},{%8,%9},{%0,%1,%2,%3};"
                 : "+f"(c[0]), "+f"(c[1]), "+f"(c[2]), "+f"(c[3])
                 : "r"(a[0]), "r"(a[1]), "r"(a[2]), "r"(a[3]), "r"(b0), "r"(b1));
}

// Block floating point quant: m = block max (>=0), v >= 0.
__device__ __forceinline__ float bfq(float v, float m) {
    if (m <= 0.f) return v;
    int fe = ilogbf(m);
    fe = fe < -4 ? -4 : (fe > 3 ? 3 : fe);
    float inv  = __int_as_float((127 + 3 - fe) << 23);
    float step = __int_as_float((127 - 3 + fe) << 23);
    float r = rintf(v * inv);
    r = fminf(r, 15.f);
    return r * step;
}

// ---------------------------------------------------------------------------
// Prep kernels
// ---------------------------------------------------------------------------
__global__ void bnprep_kernel(
    const float* __restrict__ g1, const float* __restrict__ b1,
    const float* __restrict__ mu1, const float* __restrict__ var1,
    const float* __restrict__ g2, const float* __restrict__ b2,
    const float* __restrict__ mu2, const float* __restrict__ var2,
    const float* __restrict__ g3, const float* __restrict__ b3,
    const float* __restrict__ mu3, const float* __restrict__ var3)
{
    int c = threadIdx.x;
    if (c < C_MID) {
        float inv = g1[c] * rsqrtf(var1[c] + BN_EPS);
        g_s1[c] = inv; g_h1[c] = b1[c] - mu1[c] * inv;     // fp32 conv1: no scale fold
        inv = g2[c] * rsqrtf(var2[c] + BN_EPS);
        g_s2[c] = inv * INV2048; g_h2[c] = b2[c] - mu2[c] * inv;
    }
    if (c < C_IN) {
        float inv = g3[c] * rsqrtf(var3[c] + BN_EPS);
        g_s3[c] = inv * INV2048; g_h3[c] = b3[c] - mu3[c] * inv;
    }
}

__global__ void wprep_k(const float* __restrict__ w2, const float* __restrict__ w3)
{
    int idx = blockIdx.x * blockDim.x + threadIdx.x;
    const int N2 = 9 * C_MID * C_MID, N3 = C_IN * C_MID;
    if (idx < N2) {
        int tap = idx / (C_MID * C_MID);
        int r = idx % (C_MID * C_MID);
        int co = r >> 7, ci = r & 127;
        float fs = w2[(size_t)(co * C_MID + ci) * 9 + tap] * 2048.0f;
        __half hi = __float2half_rn(fs);
        g_w2h[idx] = hi; g_w2l[idx] = __float2half_rn(fs - __half2float(hi));
    } else if (idx < N2 + N3) {
        int j = idx - N2;
        float fs = w3[j] * 2048.0f;
        __half hi = __float2half_rn(fs);
        g_w3h[j] = hi; g_w3l[j] = __float2half_rn(fs - __half2float(hi));
    }
}

// ---------------------------------------------------------------------------
// conv1 (R1-proven): per-image fp32 GEMM [128x512]@[512x784], BN1+ReLU.
// CTA tile 128(M) x 112(cols), K chunks of 32, 256 thr, 8x7 per-thread.
// ---------------------------------------------------------------------------
__global__ __launch_bounds__(256, 2)
void gemm1x1_kernel(const float* __restrict__ A, const float* __restrict__ B,
                    float* __restrict__ Cout,
                    const float* __restrict__ scale, const float* __restrict__ shift,
                    int K, int Mtot)
{
    __shared__ __align__(16) float a_s[32 * 128];
    __shared__ __align__(16) float b_s[32 * 112];

    const int n = blockIdx.y;
    const int col0 = blockIdx.x * 112;

    const float* Ab = A;
    const float* Bn = B + (size_t)n * K * HW + col0;

    const int t = threadIdx.x;
    const int tx = t & 15, ty = t >> 4;

    const int aco = t >> 1;
    const int akk = (t & 1) << 4;
    const float* ag = Ab + (size_t)aco * K + akk;
    const int brow = t >> 3;
    const int bcol = t & 7;
    const float* bg = Bn + brow * HW + bcol;

    float4 pa[4];
    float pb[14];
#pragma unroll
    for (int q = 0; q < 4; q++) pa[q] = *(const float4*)(ag + 4 * q);
#pragma unroll
    for (int j = 0; j < 14; j++) pb[j] = bg[8 * j];

    float acc[8][7];
#pragma unroll
    for (int i = 0; i < 8; i++)
#pragma unroll
        for (int j = 0; j < 7; j++) acc[i][j] = 0.f;

    for (int k0 = 0; k0 < K; k0 += 32) {
        __syncthreads();
#pragma unroll
        for (int q = 0; q < 4; q++) {
            a_s[(akk + 4 * q + 0) * 128 + aco] = pa[q].x;
            a_s[(akk + 4 * q + 1) * 128 + aco] = pa[q].y;
            a_s[(akk + 4 * q + 2) * 128 + aco] = pa[q].z;
            a_s[(akk + 4 * q + 3) * 128 + aco] = pa[q].w;
        }
#pragma unroll
        for (int j = 0; j < 14; j++) b_s[brow * 112 + bcol + 8 * j] = pb[j];
        __syncthreads();

        if (k0 + 32 < K) {
            const float* ag2 = ag + k0 + 32;
#pragma unroll
            for (int q = 0; q < 4; q++) pa[q] = *(const float4*)(ag2 + 4 * q);
            const float* bg2 = bg + (size_t)(k0 + 32) * HW;
#pragma unroll
            for (int j = 0; j < 14; j++) pb[j] = bg2[8 * j];
        }

#pragma unroll 8
        for (int kk = 0; kk < 32; kk++) {
            float4 a0 = *(const float4*)&a_s[kk * 128 + ty * 8];
            float4 a1 = *(const float4*)&a_s[kk * 128 + ty * 8 + 4];
            float av[8] = {a0.x, a0.y, a0.z, a0.w, a1.x, a1.y, a1.z, a1.w};
            float bv[7];
#pragma unroll
            for (int j = 0; j < 7; j++) bv[j] = b_s[kk * 112 + tx + 16 * j];
#pragma unroll
            for (int i = 0; i < 8; i++)
#pragma unroll
                for (int j = 0; j < 7; j++)
                    acc[i][j] = fmaf(av[i], bv[j], acc[i][j]);
        }
    }

#pragma unroll
    for (int i = 0; i < 8; i++) {
        int ch = ty * 8 + i;
        float s = scale[ch], h = shift[ch];
        size_t ob = ((size_t)n * Mtot + ch) * HW + col0;
#pragma unroll
        for (int j = 0; j < 7; j++) {
            float v = fmaf(acc[i][j], s, h);
            Cout[ob + tx + 16 * j] = fmaxf(v, 0.f);
        }
    }
}

// ---------------------------------------------------------------------------
// quant (R1-proven, in place on fp32): blocks of 32 channels per pixel.
// ---------------------------------------------------------------------------
__global__ void quant_kernel(float* __restrict__ p, int C, int total)
{
    int idx = blockIdx.x * blockDim.x + threadIdx.x;
    if (idx >= total) return;
    int hw = idx % HW;
    int nb = idx / HW;
    int nblk = C >> 5;
    int b = nb % nblk;
    int n = nb / nblk;
    float* q = p + ((size_t)(n * C + b * 32)) * HW + hw;

    float v[32];
    float ma = 0.f;
#pragma unroll
    for (int c = 0; c < 32; c++) {
        v[c] = q[c * HW];
        ma = fmaxf(ma, fabsf(v[c]));
    }
    if (ma > 0.f) {
        int e;
        frexpf(ma, &e);
        int fe = e - 1;
        if (fe < -4) fe = -4;
        if (fe > 3) fe = 3;
        float step = ldexpf(1.0f, fe - 3);
        float inv = ldexpf(1.0f, 3 - fe);
#pragma unroll
        for (int c = 0; c < 32; c++) {
            float r = rintf(v[c] * inv);
            r = fminf(fmaxf(r, -16.f), 15.f);
            q[c * HW] = r * step;
        }
    }
}

// ---------------------------------------------------------------------------
// repack quantized fp32 t1f -> fp16 halo-padded t1p + shifted twin t1pm
// ---------------------------------------------------------------------------
__global__ void repack_k()
{
    size_t i = (size_t)blockIdx.x * 256 + threadIdx.x;
    const size_t total = (size_t)NIMG * C_MID * HW;
    if (i >= total) return;
    int hw = (int)(i % HW);
    size_t ch = i / HW;          // n*C_MID + c
    int y = hw / 28, x = hw - y * 28;
    __half hq = __float2half_rn(g_t1f[i]);   // quantized values are exact in fp16
    size_t chb = ch * CH_PAD + (size_t)(y + 1) * 32 + x;
    g_t1p [chb + 2] = hq;
    g_t1pm[chb + 3] = hq;
}

// ---------------------------------------------------------------------------
// HMMA staging (conv2 / conv3)
// ---------------------------------------------------------------------------
__device__ __forceinline__ void stageA(uint32_t ab, const __half* src, int rstride, int tid)
{
#pragma unroll
    for (int i = 0; i < 4; i++) {
        int idx = tid + i * 256;
        int r = idx >> 3, s = idx & 7;
        CPA16(ab + swz(r * 128 + s * 16), src + (size_t)r * rstride + s * 8);
    }
}
__device__ __forceinline__ void stageB16(uint32_t bb, const __half* src, int tid)
{
    for (int idx = tid; idx < 896; idx += 256) {
        int r = idx / 14, s = idx % 14;
        CPA16(bb + r * 240 + s * 16, src + (size_t)r * HW + s * 8);
    }
}
// conv2 B: 64 k-rows x 112 out-pixels from padded layout; zeros from halo.
__device__ __forceinline__ void stageB_pad(uint32_t bb, const __half* src,
                                           long long chb, int y0, int dy, int qoff, int tid)
{
    for (int idx = tid; idx < 3584; idx += 256) {
        int r = idx / 56, t = idx % 56;
        int rimg = t / 14, w = t % 14;
        const __half* s = src + (chb + r) * CH_PAD + (y0 + rimg + dy + 1) * 32 + qoff + 2 * w;
        CPA4(bb + r * 240 + (rimg * 28 + 2 * w) * 2, s);
    }
}

template <int MODE>   // 1: conv2, 2: conv3
__device__ __forceinline__ void stage_chunk(int c, uint32_t ab, uint32_t bb,
                                            int n, int p0, int MB, int tid)
{
    if (MODE == 1) {
        int tap = c >> 2, wsel = (c >> 1) & 1, kc = c & 1;  // lo first
        const __half* aw = (wsel ? g_w2h : g_w2l) + (size_t)tap * C_MID * C_MID + kc * 64;
        stageA(ab, aw, C_MID, tid);
        int dy = tap / 3 - 1, dx = tap % 3 - 1;
        long long chb = (long long)n * C_MID + kc * 64;
        int y0 = p0 / 28;
        if (dx & 1) stageB_pad(bb, g_t1pm, chb, y0, dy, dx + 3, tid);
        else        stageB_pad(bb, g_t1p,  chb, y0, dy, dx + 2, tid);
    } else {
        int po = c >> 1, kc = c & 1;   // po 0=lo, 1=hi
        const __half* aw = (po ? g_w3h : g_w3l) + (size_t)MB * C_MID + kc * 64;
        stageA(ab, aw, C_MID, tid);
        stageB16(bb, g_t2 + ((size_t)n * C_MID + kc * 64) * HW + p0, tid);
    }
    CPCOMMIT();
}

// ---------------------------------------------------------------------------
// HMMA conv kernel (MODE 1: conv2, 2: conv3)
// ---------------------------------------------------------------------------
template <int MODE>
__global__ __launch_bounds__(256, 2) void conv_k(const float* __restrict__ xres,
                                                 float* __restrict__ out)
{
    extern __shared__ __align__(1024) char smraw[];
    const uint32_t sbase = smem_u32(smraw);
    const uint32_t sA0 = sbase, sA1 = sbase + 16384;
    const uint32_t sB0 = sbase + 32768, sB1 = sbase + 32768 + 15360;

    const int tid = threadIdx.x, wid = tid >> 5, lane = tid & 31;
    const int bx = blockIdx.x, p0 = bx * 112;
    const int n = (MODE == 2) ? blockIdx.z : blockIdx.y;
    const int MB = (MODE == 2) ? blockIdx.y * 128 : 0;
    const int NC = (MODE == 1) ? 36 : 4;

    const int m0 = (wid >> 1) * 32;
    const int n0w = (wid & 1) * 56;

    float acc[2][7][4];
#pragma unroll
    for (int mt = 0; mt < 2; mt++)
#pragma unroll
        for (int nt = 0; nt < 7; nt++)
#pragma unroll
            for (int e = 0; e < 4; e++) acc[mt][nt][e] = 0.f;

    stage_chunk<MODE>(0, sA0, sB0, n, p0, MB, tid);

    for (int c = 0; c < NC; c++) {
        const uint32_t cab = (c & 1) ? sA1 : sA0;
        const uint32_t cbb = (c & 1) ? sB1 : sB0;
        if (c + 1 < NC) {
            stage_chunk<MODE>(c + 1, (c & 1) ? sA0 : sA1, (c & 1) ? sB0 : sB1, n, p0, MB, tid);
            CPWAIT1();
        } else {
            CPWAIT0();
        }
        __syncthreads();

#pragma unroll
        for (int kk = 0; kk < 4; kk++) {
            uint32_t a[2][4];
#pragma unroll
            for (int mt = 0; mt < 2; mt++) {
                int r = m0 + mt * 16 + (lane & 15);
                int kb = (kk * 16 + ((lane >> 4) << 3)) * 2;
                ldsm_x4(a[mt], cab + swz(r * 128 + kb));
            }
#pragma unroll
            for (int nt = 0; nt < 7; nt++) {
                uint32_t b0, b1;
                int kr = kk * 16 + (lane & 15);
                ldsm_x2t(b0, b1, cbb + kr * 240 + (n0w + nt * 8) * 2);
#pragma unroll
                for (int mt = 0; mt < 2; mt++) mma16816(acc[mt][nt], a[mt], b0, b1);
            }
        }
        __syncthreads();
    }

    // Epilogue: BN (scale includes 2^-11) + (residual) + ReLU + quant + store
    const float* S  = (MODE == 1) ? g_s2 : g_s3;
    const float* Hs = (MODE == 1) ? g_h2 : g_h3;
    const int rq = lane >> 2, cq = (lane & 3) * 2;
    const int coW = MB + m0;
    const size_t imgB = (size_t)n * C_MID;
    const size_t imgB5 = (size_t)n * C_IN;

    float sj[4], hj[4];
#pragma unroll
    for (int j = 0; j < 4; j++) {
        int cc = coW + 8 * j + rq;
        sj[j] = S[cc]; hj[j] = Hs[cc];
    }

#pragma unroll
    for (int nt = 0; nt < 7; nt++) {
        int c0 = n0w + nt * 8 + cq;
        float v[2][4];
#pragma unroll
        for (int mt = 0; mt < 2; mt++)
#pragma unroll
            for (int e = 0; e < 4; e++) {
                int j = 2 * mt + (e >> 1);
                v[mt][e] = fmaf(acc[mt][nt][e], sj[j], hj[j]);
            }
        if (MODE == 2) {
#pragma unroll
            for (int mt = 0; mt < 2; mt++) {
                int r1 = coW + 16 * mt + rq;
                float2 ra = *(const float2*)(xres + (imgB5 + r1) * HW + p0 + c0);
                float2 rb = *(const float2*)(xres + (imgB5 + r1 + 8) * HW + p0 + c0);
                v[mt][0] += ra.x; v[mt][1] += ra.y;
                v[mt][2] += rb.x; v[mt][3] += rb.y;
            }
        }
#pragma unroll
        for (int mt = 0; mt < 2; mt++)
#pragma unroll
            for (int e = 0; e < 4; e++) v[mt][e] = fmaxf(v[mt][e], 0.f);

        float em = fmaxf(fmaxf(v[0][0], v[0][2]), fmaxf(v[1][0], v[1][2]));
        float om = fmaxf(fmaxf(v[0][1], v[0][3]), fmaxf(v[1][1], v[1][3]));
#pragma unroll
        for (int d = 4; d < 32; d <<= 1) {
            em = fmaxf(em, __shfl_xor_sync(0xffffffffu, em, d));
            om = fmaxf(om, __shfl_xor_sync(0xffffffffu, om, d));
        }

        if (MODE == 2) {
#pragma unroll
            for (int mt = 0; mt < 2; mt++) {
                int r1 = coW + 16 * mt + rq;
                float2 o1, o2;
                o1.x = bfq(v[mt][0], em); o1.y = bfq(v[mt][1], om);
                o2.x = bfq(v[mt][2], em); o2.y = bfq(v[mt][3], om);
                *(float2*)(out + (imgB5 + r1) * HW + p0 + c0) = o1;
                *(float2*)(out + (imgB5 + r1 + 8) * HW + p0 + c0) = o2;
            }
        } else {
#pragma unroll
            for (int mt = 0; mt < 2; mt++)
#pragma unroll
                for (int e = 0; e < 4; e++) {
                    int cc = coW + 16 * mt + 8 * (e >> 1) + rq;
                    int p = p0 + c0 + (e & 1);
                    __half hq = __float2half_rn(bfq(v[mt][e], (e & 1) ? om : em));
                    g_t2[(imgB + cc) * HW + p] = hq;
                }
        }
    }
}

// ---------------------------------------------------------------------------
// Launcher
// ---------------------------------------------------------------------------
extern "C" void kernel_launch(void* const* d_in, const int* in_sizes, int n_in,
                              void* d_out, int out_size)
{
    (void)n_in; (void)out_size;

    int iw1, iw2, iw3, ibn1, ibn2, ibn3;
    if (in_sizes[2] == 147456) {
        iw1 = 1; iw2 = 2; iw3 = 3; ibn1 = 4; ibn2 = 8; ibn3 = 12;
    } else {
        iw1 = 1; ibn1 = 2; iw2 = 6; ibn2 = 7; iw3 = 11; ibn3 = 12;
    }

    const float* x  = (const float*)d_in[0];
    const float* w1 = (const float*)d_in[iw1];
    const float* w2 = (const float*)d_in[iw2];
    const float* w3 = (const float*)d_in[iw3];
    const float* g1 = (const float*)d_in[ibn1 + 0];
    const float* b1 = (const float*)d_in[ibn1 + 1];
    const float* mu1 = (const float*)d_in[ibn1 + 2];
    const float* var1 = (const float*)d_in[ibn1 + 3];
    const float* g2 = (const float*)d_in[ibn2 + 0];
    const float* b2 = (const float*)d_in[ibn2 + 1];
    const float* mu2 = (const float*)d_in[ibn2 + 2];
    const float* var2 = (const float*)d_in[ibn2 + 3];
    const float* g3 = (const float*)d_in[ibn3 + 0];
    const float* b3 = (const float*)d_in[ibn3 + 1];
    const float* mu3 = (const float*)d_in[ibn3 + 2];
    const float* var3 = (const float*)d_in[ibn3 + 3];
    float* out = (float*)d_out;

    float* t1f;
    cudaGetSymbolAddress((void**)&t1f, g_t1f);
    float *s1, *h1;
    cudaGetSymbolAddress((void**)&s1, g_s1);
    cudaGetSymbolAddress((void**)&h1, g_h1);

    const int SMEM = 63488;
    cudaFuncSetAttribute(conv_k<1>, cudaFuncAttributeMaxDynamicSharedMemorySize, SMEM);
    cudaFuncSetAttribute(conv_k<2>, cudaFuncAttributeMaxDynamicSharedMemorySize, SMEM);

    bnprep_kernel<<<1, 512>>>(g1, b1, mu1, var1, g2, b2, mu2, var2, g3, b3, mu3, var3);
    {
        int total = 9 * C_MID * C_MID + C_IN * C_MID;
        wprep_k<<<(total + 255) / 256, 256>>>(w2, w3);
    }

    // conv1 fp32 (proven) + BN1 + ReLU
    gemm1x1_kernel<<<dim3(7, NIMG), 256>>>(w1, x, t1f, s1, h1, 512, C_MID);
    // quant (proven) in place
    quant_kernel<<<(NIMG * 4 * HW + 255) / 256, 256>>>(t1f, C_MID, NIMG * 4 * HW);
    // repack to fp16 padded
    {
        size_t total = (size_t)NIMG * C_MID * HW;
        repack_k<<<(int)((total + 255) / 256), 256>>>();
    }

    conv_k<1><<<dim3(7, NIMG, 1), 256, SMEM>>>(nullptr, nullptr);
    conv_k<2><<<dim3(7, 4, NIMG), 256, SMEM>>>(x, out);
}